// round 3
// baseline (speedup 1.0000x reference)
#include <cuda_runtime.h>
#include <math.h>

// AttFusion, register-resident: out[g,c,s] = sum_m softmax_m(<x0,xm>_c/16) x[m,c,s].
// x: [28, 256, 8448] fp32; out: [8, 256, 8448] fp32.
// Thread owns (c, part): one float4 (4 spatial positions) per agent m, kept in
// registers end-to-end. Dot products reduced over c via warp shuffles; only the
// tiny score/weight buffers touch smem.

#define C_DIM   256
#define S_DIM   8448            // 48*176
#define T_POS   8               // positions per block (2 float4 parts)
#define N_MAX   5
#define N_GROUP 8

__device__ __constant__ int c_off[N_GROUP] = {0, 2, 5, 9, 14, 17, 19, 23};
__device__ __constant__ int c_len[N_GROUP] = {2, 3, 4, 5, 3, 2, 4, 5};

__global__ __launch_bounds__(512, 2)
void attfusion_kernel(const float* __restrict__ x, float* __restrict__ out) {
    __shared__ float red[16][2][N_MAX][4];   // [warp][part][m][pos]
    __shared__ float wsm[N_MAX][T_POS];      // softmax weights per position

    const int g    = blockIdx.y;
    const int n    = c_len[g];
    const int off  = c_off[g];
    const int s0   = blockIdx.x * T_POS;
    const int tid  = threadIdx.x;
    const int part = tid & 1;                // which float4 of the 8 positions
    const int c    = tid >> 1;               // channel 0..255
    const int lane = tid & 31;               // = 2*(c&15) + part
    const int warp = tid >> 5;

    // ---- Load: n float4s, independent, front-batched. Lane pairs cover a
    // contiguous 32B segment per (m,c) row -> full-sector coalescing. ----
    const float* xg = x + (size_t)(off * C_DIM + c) * S_DIM + s0 + part * 4;
    float4 xv[N_MAX];
#pragma unroll
    for (int m = 0; m < N_MAX; m++) {
        if (m < n) {
            xv[m] = *reinterpret_cast<const float4*>(xg + (size_t)m * C_DIM * S_DIM);
        } else {
            xv[m] = make_float4(0.f, 0.f, 0.f, 0.f);
        }
    }

    // ---- Per-channel products (the dot integrand), then reduce over the 16
    // c-values in this warp (c occupies lane bits 1..4 -> strides 2,4,8,16). ----
    float p[N_MAX][4];
#pragma unroll
    for (int m = 0; m < N_MAX; m++) {
        p[m][0] = xv[0].x * xv[m].x;
        p[m][1] = xv[0].y * xv[m].y;
        p[m][2] = xv[0].z * xv[m].z;
        p[m][3] = xv[0].w * xv[m].w;
    }
#pragma unroll
    for (int m = 0; m < N_MAX; m++) {
        if (m < n) {                          // n is block-uniform: safe branch
#pragma unroll
            for (int d = 2; d <= 16; d <<= 1) {
#pragma unroll
                for (int j = 0; j < 4; j++)
                    p[m][j] += __shfl_down_sync(0xffffffffu, p[m][j], d);
            }
        }
    }
    if (lane < 2) {                           // lane==part holds the c-sum
#pragma unroll
        for (int m = 0; m < N_MAX; m++)
            if (m < n) {
#pragma unroll
                for (int j = 0; j < 4; j++)
                    red[warp][lane][m][j] = p[m][j];
            }
    }
    __syncthreads();

    // ---- Cross-warp reduce + softmax: one thread per spatial position. ----
    if (tid < T_POS) {
        const int pp = tid >> 2, jj = tid & 3;
        float d[N_MAX];
#pragma unroll
        for (int m = 0; m < N_MAX; m++) {
            if (m < n) {
                float a = 0.0f;
#pragma unroll
                for (int w = 0; w < 16; w++) a += red[w][pp][m][jj];
                d[m] = a * 0.0625f;           // 1/sqrt(256)
            } else {
                d[m] = -1e30f;
            }
        }
        float mx = d[0];
#pragma unroll
        for (int m = 1; m < N_MAX; m++) mx = fmaxf(mx, d[m]);
        float e[N_MAX], sumv = 0.0f;
#pragma unroll
        for (int m = 0; m < N_MAX; m++)
            if (m < n) { e[m] = __expf(d[m] - mx); sumv += e[m]; }
        const float inv = 1.0f / sumv;
#pragma unroll
        for (int m = 0; m < N_MAX; m++)
            if (m < n) wsm[m][tid] = e[m] * inv;
    }
    __syncthreads();

    // ---- Weighted sum from registers, one float4 store. ----
    float4 acc = make_float4(0.f, 0.f, 0.f, 0.f);
#pragma unroll
    for (int m = 0; m < N_MAX; m++) {
        if (m < n) {
            const float* wrow = &wsm[m][part * 4];
            acc.x += wrow[0] * xv[m].x;
            acc.y += wrow[1] * xv[m].y;
            acc.z += wrow[2] * xv[m].z;
            acc.w += wrow[3] * xv[m].w;
        }
    }
    float* og = out + (size_t)(g * C_DIM + c) * S_DIM + s0 + part * 4;
    *reinterpret_cast<float4*>(og) = acc;
}

extern "C" void kernel_launch(void* const* d_in, const int* in_sizes, int n_in,
                              void* d_out, int out_size) {
    const float* x = (const float*)d_in[0];
    float* out = (float*)d_out;

    dim3 grid(S_DIM / T_POS, N_GROUP);        // 1056 x 8 = 8448 blocks
    attfusion_kernel<<<grid, 512>>>(x, out);
}

// round 4
// speedup vs baseline: 1.1846x; 1.1846x over previous
#include <cuda_runtime.h>
#include <math.h>

// AttFusion: out[g,c,s] = sum_m softmax_m(<x0,xm>_c / 16) * x[m,c,s]
// x: [28, 256, 8448] fp32; out: [8, 256, 8448] fp32.
//
// R4: lane-along-s mapping. Block = (group, 128 s-positions), 256 threads.
// Warp w owns channels [32w, 32w+32); lane l owns the float4 at s0+4l.
// Every global access is a 512B contiguous, 128B-aligned warp transaction
// (minimal L1 wavefronts). Pass 1 accumulates partial dots over the warp's
// channels; cross-warp reduce + softmax in smem; pass 2 re-reads the slab
// (L2-hot) and writes the weighted sum.

#define C_DIM   256
#define S_DIM   8448            // 48*176, divisible by 128
#define T_POS   128             // s positions per block
#define N_MAX   5
#define N_GROUP 8
#define NWARPS  8
#define C_PER_W 32              // channels per warp

__device__ __constant__ int c_off[N_GROUP] = {0, 2, 5, 9, 14, 17, 19, 23};
__device__ __constant__ int c_len[N_GROUP] = {2, 3, 4, 5, 3, 2, 4, 5};

__global__ __launch_bounds__(256, 4)
void attfusion_kernel(const float* __restrict__ x, float* __restrict__ out) {
    __shared__ float red[N_MAX][NWARPS][T_POS];  // 20 KB: partial dots
    __shared__ float wsm[N_MAX][T_POS];          // 2.5 KB: softmax weights

    const int g    = blockIdx.y;
    const int n    = c_len[g];
    const int off  = c_off[g];
    const int s0   = blockIdx.x * T_POS;
    const int tid  = threadIdx.x;
    const int lane = tid & 31;
    const int warp = tid >> 5;
    const int c0   = warp * C_PER_W;

    const size_t mstride = (size_t)C_DIM * S_DIM;           // per-agent stride
    const float* xb = x + (size_t)(off * C_DIM + c0) * S_DIM + s0 + lane * 4;

    // ---- Pass 1: partial dot products over this warp's 32 channels ----
    float p[N_MAX][4];
#pragma unroll
    for (int m = 0; m < N_MAX; m++)
#pragma unroll
        for (int j = 0; j < 4; j++) p[m][j] = 0.0f;

    {
        const float* ptr = xb;
#pragma unroll 2
        for (int k = 0; k < C_PER_W; k++) {
            float4 xv[N_MAX];
#pragma unroll
            for (int m = 0; m < N_MAX; m++)
                if (m < n)
                    xv[m] = *reinterpret_cast<const float4*>(ptr + m * mstride);
#pragma unroll
            for (int m = 0; m < N_MAX; m++) {
                if (m < n) {
                    p[m][0] += xv[0].x * xv[m].x;
                    p[m][1] += xv[0].y * xv[m].y;
                    p[m][2] += xv[0].z * xv[m].z;
                    p[m][3] += xv[0].w * xv[m].w;
                }
            }
            ptr += S_DIM;
        }
    }
#pragma unroll
    for (int m = 0; m < N_MAX; m++)
        if (m < n)
            *reinterpret_cast<float4*>(&red[m][warp][lane * 4]) =
                make_float4(p[m][0], p[m][1], p[m][2], p[m][3]);
    __syncthreads();

    // ---- Reduce across warps + softmax: threads 0..127, one s each ----
    if (tid < T_POS) {
        float d[N_MAX];
#pragma unroll
        for (int m = 0; m < N_MAX; m++) {
            if (m < n) {
                float a = 0.0f;
#pragma unroll
                for (int w = 0; w < NWARPS; w++) a += red[m][w][tid];
                d[m] = a * 0.0625f;                          // 1/sqrt(256)
            } else {
                d[m] = -1e30f;
            }
        }
        float mx = d[0];
#pragma unroll
        for (int m = 1; m < N_MAX; m++) mx = fmaxf(mx, d[m]);
        float e[N_MAX], sumv = 0.0f;
#pragma unroll
        for (int m = 0; m < N_MAX; m++)
            if (m < n) { e[m] = __expf(d[m] - mx); sumv += e[m]; }
        const float inv = 1.0f / sumv;
#pragma unroll
        for (int m = 0; m < N_MAX; m++)
            if (m < n) wsm[m][tid] = e[m] * inv;
    }
    __syncthreads();

    // ---- Pass 2: weighted sum. Slab is L2-hot; weights in registers ----
    float4 wv[N_MAX];
#pragma unroll
    for (int m = 0; m < N_MAX; m++)
        if (m < n)
            wv[m] = *reinterpret_cast<const float4*>(&wsm[m][lane * 4]);

    {
        const float* ptr = xb;
        float* optr = out + (size_t)(g * C_DIM + c0) * S_DIM + s0 + lane * 4;
#pragma unroll 2
        for (int k = 0; k < C_PER_W; k++) {
            float4 xv[N_MAX];
#pragma unroll
            for (int m = 0; m < N_MAX; m++)
                if (m < n)
                    xv[m] = *reinterpret_cast<const float4*>(ptr + m * mstride);
            float4 acc = make_float4(0.f, 0.f, 0.f, 0.f);
#pragma unroll
            for (int m = 0; m < N_MAX; m++) {
                if (m < n) {
                    acc.x += wv[m].x * xv[m].x;
                    acc.y += wv[m].y * xv[m].y;
                    acc.z += wv[m].z * xv[m].z;
                    acc.w += wv[m].w * xv[m].w;
                }
            }
            *reinterpret_cast<float4*>(optr) = acc;
            ptr  += S_DIM;
            optr += S_DIM;
        }
    }
}

extern "C" void kernel_launch(void* const* d_in, const int* in_sizes, int n_in,
                              void* d_out, int out_size) {
    const float* x = (const float*)d_in[0];
    float* out = (float*)d_out;

    dim3 grid(S_DIM / T_POS, N_GROUP);           // 66 x 8 = 528 blocks
    attfusion_kernel<<<grid, 256>>>(x, out);
}